// round 1
// baseline (speedup 1.0000x reference)
#include <cuda_runtime.h>
#include <cstdint>

// Problem constants (fixed by reference)
#define SORB  64
#define NELE  32
#define HID   256
#define BATCH 8192
#define LEN   1056      // (SORB+2)*SORB/4
#define ALPHA 16        // NELE/2
#define NSTEP 32        // SORB/2

// Kernel tiling
#define WARPS 8         // warps per block
#define TB    4         // batch elements per warp
#define SPAD  66        // padded smem row stride (floats) for weight tile, max k+2 = 64

// cos(t) for |t| < 0.07: 1 - t^2/2 + t^4/24, abs err < 2e-10
__device__ __forceinline__ float cospoly(float t) {
    float t2 = t * t;
    return fmaf(t2, fmaf(t2, 0.0416666667f, -0.5f), 1.0f);
}

__global__ __launch_bounds__(WARPS * 32)
void rbm_sites_kernel(const int* __restrict__ x,
                      const float* __restrict__ W,
                      const float* __restrict__ hb,
                      float* __restrict__ out)
{
    extern __shared__ float sm[];
    float* ws = sm;                 // [HID][SPAD] weight tile for current step
    float* bs = sm + HID * SPAD;    // [HID] hidden bias

    const int tid  = threadIdx.x;
    const int lane = tid & 31;
    const int wid  = tid >> 5;

    if (tid < HID) bs[tid] = hb[tid];

    // This warp's batch elements
    const int b0 = (blockIdx.x * WARPS + wid) * TB;

    // Pack x01 bits: bit j of (xlo,xhi) = (x[b, j] > 0)
    unsigned xlo[TB], xhi[TB];
#pragma unroll
    for (int t = 0; t < TB; ++t) {
        const int b = b0 + t;
        int v0 = x[(size_t)b * SORB + lane];
        int v1 = x[(size_t)b * SORB + 32 + lane];
        xlo[t] = __ballot_sync(0xffffffffu, v0 > 0);
        xhi[t] = __ballot_sync(0xffffffffu, v1 > 0);
    }

    float prob[TB];
    int   nu[TB], nd[TB];
#pragma unroll
    for (int t = 0; t < TB; ++t) { prob[t] = 1.0f; nu[t] = 0; nd[t] = 0; }

    __syncthreads();

    for (int m = 0; m < NSTEP; ++m) {
        const int k     = 2 * m;
        const int start = m * (m + 1);   // first column of this step's weight block
        const int wcols = k + 2;

        // Stage weight tile: thread tid = hidden row h, copies wcols floats.
        // Both gmem (start even) and smem (SPAD*4 = 264, mult of 8) are 8B aligned.
        {
            const float2* g = (const float2*)(W + (size_t)tid * LEN + start);
            float2*       d = (float2*)(ws + tid * SPAD);
            for (int j2 = 0; j2 < (wcols >> 1); ++j2) d[j2] = g[j2];
        }
        __syncthreads();

        // theta_c accumulation: lane owns h = i*32 + lane, i = 0..7
        float theta[TB][8];
#pragma unroll
        for (int i = 0; i < 8; ++i) {
            const float bv = bs[i * 32 + lane];
#pragma unroll
            for (int t = 0; t < TB; ++t) theta[t][i] = bv;
        }

        for (int j = 0; j < k; j += 2) {
            float2 wv[8];
#pragma unroll
            for (int i = 0; i < 8; ++i)
                wv[i] = *(const float2*)(ws + (i * 32 + lane) * SPAD + j);
            const unsigned sh = (unsigned)(j & 31);
#pragma unroll
            for (int t = 0; t < TB; ++t) {
                const unsigned word = (j < 32) ? xlo[t] : xhi[t];
                const bool bA = (word >> sh) & 1u;
                const bool bB = (word >> (sh + 1)) & 1u;
#pragma unroll
                for (int i = 0; i < 8; ++i) {
                    if (bA) theta[t][i] += wv[i].x;
                    if (bB) theta[t][i] += wv[i].y;
                }
            }
        }

        // value products over this lane's 8 hidden units, 4 spin states
        float pr[TB][4];
#pragma unroll
        for (int t = 0; t < TB; ++t) {
            pr[t][0] = 1.0f; pr[t][1] = 1.0f; pr[t][2] = 1.0f; pr[t][3] = 1.0f;
        }
#pragma unroll
        for (int i = 0; i < 8; ++i) {
            const int h = i * 32 + lane;
            const float w0  = ws[h * SPAD + k];
            const float w1  = ws[h * SPAD + k + 1];
            const float w01 = w0 + w1;
#pragma unroll
            for (int t = 0; t < TB; ++t) {
                const float tc = theta[t][i];
                pr[t][0] *= cospoly(tc);
                pr[t][1] *= cospoly(tc + w0);
                pr[t][2] *= cospoly(tc + w1);
                pr[t][3] *= cospoly(tc + w01);
            }
        }

        // Butterfly product-reduce across the warp (all lanes end with full product)
#pragma unroll
        for (int t = 0; t < TB; ++t) {
#pragma unroll
            for (int s = 0; s < 4; ++s) {
                float p = pr[t][s];
                p *= __shfl_xor_sync(0xffffffffu, p, 16);
                p *= __shfl_xor_sync(0xffffffffu, p, 8);
                p *= __shfl_xor_sync(0xffffffffu, p, 4);
                p *= __shfl_xor_sync(0xffffffffu, p, 2);
                p *= __shfl_xor_sync(0xffffffffu, p, 1);
                pr[t][s] = p;
            }
        }

        // Scalar per-batch update (replicated identically across all lanes)
#pragma unroll
        for (int t = 0; t < TB; ++t) {
            float v0 = pr[t][0], v1 = pr[t][1], v2 = pr[t][2], v3 = pr[t][3];
            float n1 = sqrtf(v0 * v0 + v1 * v1 + v2 * v2 + v3 * v3);
            float inv1 = 1.0f / fmaxf(n1, 1e-12f);
            v0 *= inv1; v1 *= inv1; v2 *= inv1; v3 *= inv1;
            if (k >= ALPHA) {
                const int lower = m - 16;        // base + k/2 = (ALPHA - SORB/2) + m
                const bool ou = nu[t] < ALPHA;
                const bool uu = nu[t] > lower;
                const bool od = nd[t] < ALPHA;
                const bool ud = nd[t] > lower;
                v0 = (uu && ud) ? v0 : 0.0f;
                v1 = (ou && ud) ? v1 : 0.0f;
                v2 = (uu && od) ? v2 : 0.0f;
                v3 = (ou && od) ? v3 : 0.0f;
                float n2 = sqrtf(v0 * v0 + v1 * v1 + v2 * v2 + v3 * v3);
                float inv2 = 1.0f / fmaxf(n2, 1e-12f);
                v0 *= inv2; v1 *= inv2; v2 *= inv2; v3 *= inv2;
            }
            const unsigned word = (k < 32) ? xlo[t] : xhi[t];
            const unsigned sh = (unsigned)(k & 31);
            const int bu = (word >> sh) & 1u;
            const int bd = (word >> (sh + 1)) & 1u;
            const int st = bu + 2 * bd;
            const float vs = (st == 0) ? v0 : (st == 1) ? v1 : (st == 2) ? v2 : v3;
            prob[t] *= vs;
            nu[t] += bu;
            nd[t] += bd;
        }

        __syncthreads();   // protect ws before next step's staging
    }

    if (lane == 0) {
#pragma unroll
        for (int t = 0; t < TB; ++t) out[b0 + t] = prob[t];
    }
}

extern "C" void kernel_launch(void* const* d_in, const int* in_sizes, int n_in,
                              void* d_out, int out_size)
{
    const int*   x  = (const int*)d_in[0];
    const float* W  = (const float*)d_in[1];
    const float* hb = (const float*)d_in[2];
    float*       out = (float*)d_out;

    const size_t smem = (size_t)(HID * SPAD + HID) * sizeof(float);  // 68608 B
    cudaFuncSetAttribute(rbm_sites_kernel,
                         cudaFuncAttributeMaxDynamicSharedMemorySize, (int)smem);

    const int blocks = BATCH / (WARPS * TB);   // 256
    rbm_sites_kernel<<<blocks, WARPS * 32, smem>>>(x, W, hb, out);
}

// round 3
// speedup vs baseline: 4.0258x; 4.0258x over previous
#include <cuda_runtime.h>
#include <cstdint>

#define SORB  64
#define HID   256
#define BATCH 8192
#define LEN   1056
#define NSTEP 32
#define BPB   64        // batch elements per block (main kernel)

// Per-step precomputed quantities:
//   g_u[m][j]  = ( Σ_h W[h,start+j]·W[h,start+k],  Σ_h W[h,start+j]·W[h,start+k+1] )
//   g_cst[m]   = { c0=Σ hb·w0, c1=Σ hb·w1, Q0=Σ w0², Q1=Σ w1², Q01=Σ w0·w1 }
__device__ float2 g_u[NSTEP][64];
__device__ float  g_cst[NSTEP][5];

__global__ __launch_bounds__(256)
void precompute_kernel(const float* __restrict__ W, const float* __restrict__ hb)
{
    const int m = blockIdx.x;
    const int k = 2 * m, start = m * (m + 1), cols = k + 2;
    extern __shared__ float s[];
    float* tile = s;                 // [256][cols]
    float* w0   = s + HID * 64;      // [256]
    float* w1   = w0 + HID;          // [256]
    const int tid = threadIdx.x;

    for (int idx = tid; idx < HID * cols; idx += 256) {
        const int h = idx / cols, j = idx - h * cols;
        tile[idx] = W[(size_t)h * LEN + start + j];
    }
    __syncthreads();
    w0[tid] = tile[tid * cols + k];
    w1[tid] = tile[tid * cols + k + 1];
    __syncthreads();

    if (tid < 64) {
        float a0 = 0.f, a1 = 0.f;
        if (tid < k) {
            for (int h = 0; h < HID; ++h) {
                const float wv = tile[h * cols + tid];
                a0 = fmaf(wv, w0[h], a0);
                a1 = fmaf(wv, w1[h], a1);
            }
        }
        g_u[m][tid] = make_float2(a0, a1);
    } else if (tid < 69) {
        const int which = tid - 64;
        float acc = 0.f;
        for (int h = 0; h < HID; ++h) {
            float a, b;
            if      (which == 0) { a = hb[h]; b = w0[h]; }
            else if (which == 1) { a = hb[h]; b = w1[h]; }
            else if (which == 2) { a = w0[h]; b = w0[h]; }
            else if (which == 3) { a = w1[h]; b = w1[h]; }
            else                 { a = w0[h]; b = w1[h]; }
            acc = fmaf(a, b, acc);
        }
        g_cst[m][which] = acc;
    }
}

// exp(L) for |L| <= 0.05, rel err < 5e-8
__device__ __forceinline__ float expq(float L) {
    return fmaf(L, fmaf(L, fmaf(L, 0.16666667f, 0.5f), 1.0f), 1.0f);
}

__global__ __launch_bounds__(256)
void rbm_main_kernel(const int* __restrict__ x, float* __restrict__ out)
{
    __shared__ float2   su[NSTEP][64];
    __shared__ float    sc[NSTEP][5];
    __shared__ unsigned sxlo[BPB], sxhi[BPB];
    __shared__ float    D0s[BPB][33], D1s[BPB][33];   // padded: conflict-free

    const int tid  = threadIdx.x;
    const int lane = tid & 31, wid = tid >> 5;
    const int b0   = blockIdx.x * BPB;

    // Stage per-step tables
    for (int idx = tid; idx < NSTEP * 64; idx += 256)
        ((float2*)su)[idx] = ((const float2*)g_u)[idx];
    for (int idx = tid; idx < NSTEP * 5; idx += 256)
        ((float*)sc)[idx] = ((const float*)g_cst)[idx];

    // Pack x01 bits, coalesced: warp w handles rows 8w..8w+7
    for (int r = 0; r < 8; ++r) {
        const int row = wid * 8 + r;
        const int v0 = x[(size_t)(b0 + row) * SORB + lane];
        const int v1 = x[(size_t)(b0 + row) * SORB + 32 + lane];
        const unsigned blo = __ballot_sync(0xffffffffu, v0 > 0);
        const unsigned bhi = __ballot_sync(0xffffffffu, v1 > 0);
        if (lane == 0) { sxlo[row] = blo; sxhi[row] = bhi; }
    }
    __syncthreads();

    // Phase A: parallel dots. thread = (b, g); g owns steps m = g, g+4, ..., g+28
    {
        const int b = tid & (BPB - 1);
        const int g = tid >> 6;                  // uniform per warp
        const unsigned lo = sxlo[b], hi = sxhi[b];
        #pragma unroll
        for (int mi = 0; mi < 8; ++mi) {
            const int m = g + 4 * mi;
            const int k = 2 * m;
            float d0 = sc[m][0], d1 = sc[m][1];
            const float2* pu = su[m];
            const int j1 = k < 32 ? k : 32;
            #pragma unroll 4
            for (int j = 0; j < j1; ++j) {
                const float msk = (float)((lo >> j) & 1u);   // branchless: FADD w/ 0 or u
                const float2 uv = pu[j];
                d0 = fmaf(msk, uv.x, d0);
                d1 = fmaf(msk, uv.y, d1);
            }
            #pragma unroll 4
            for (int j = 32; j < k; ++j) {
                const float msk = (float)((hi >> (j - 32)) & 1u);
                const float2 uv = pu[j];
                d0 = fmaf(msk, uv.x, d0);
                d1 = fmaf(msk, uv.y, d1);
            }
            D0s[b][m] = d0; D1s[b][m] = d1;
        }
    }
    __syncthreads();

    // Phase B: cheap sequential chain, one thread per batch element
    if (tid < BPB) {
        const int b = tid;
        const unsigned lo = sxlo[b], hi = sxhi[b];
        float prob = 1.f;
        int nu = 0, nd = 0;
        #pragma unroll
        for (int m = 0; m < NSTEP; ++m) {
            const int k = 2 * m;
            const float d0 = D0s[b][m], d1 = D1s[b][m];
            const float L1 = -d0 - 0.5f * sc[m][2];
            const float L2 = -d1 - 0.5f * sc[m][3];
            const float L3 = L1 + L2 - sc[m][4];
            float v0 = 1.f, v1 = expq(L1), v2 = expq(L2), v3 = expq(L3);
            if (m >= 8) {                       // SYMMETRY && alpha_e <= k
                const int lower = m - 16;       // base + k/2
                const bool ou = nu < 16, uu = nu > lower;
                const bool od = nd < 16, ud = nd > lower;
                v0 = (uu && ud) ? v0 : 0.f;
                v1 = (ou && ud) ? v1 : 0.f;
                v2 = (uu && od) ? v2 : 0.f;
                v3 = (ou && od) ? v3 : 0.f;
            }
            const float n2 = v0*v0 + v1*v1 + v2*v2 + v3*v3;
            float inv = rsqrtf(fmaxf(n2, 1e-24f));
            inv = inv * fmaf(-0.5f * n2 * inv, inv, 1.5f);   // 1 Newton step
            int bu, bd;
            if (k < 32) { bu = (lo >> k) & 1;        bd = (lo >> (k + 1)) & 1; }
            else        { bu = (hi >> (k - 32)) & 1; bd = (hi >> (k - 31)) & 1; }
            const int st = bu + 2 * bd;
            const float vs = st == 0 ? v0 : st == 1 ? v1 : st == 2 ? v2 : v3;
            prob *= vs * inv;
            nu += bu; nd += bd;
        }
        out[b0 + b] = prob;
    }
}

extern "C" void kernel_launch(void* const* d_in, const int* in_sizes, int n_in,
                              void* d_out, int out_size)
{
    const int*   x   = (const int*)d_in[0];
    const float* W   = (const float*)d_in[1];
    const float* hb  = (const float*)d_in[2];
    float*       out = (float*)d_out;

    const size_t psm = (size_t)(HID * 64 + 2 * HID) * sizeof(float);   // 67584 B
    cudaFuncSetAttribute(precompute_kernel,
                         cudaFuncAttributeMaxDynamicSharedMemorySize, (int)psm);

    precompute_kernel<<<NSTEP, 256, psm>>>(W, hb);
    rbm_main_kernel<<<BATCH / BPB, 256>>>(x, out);
}

// round 5
// speedup vs baseline: 19.0099x; 4.7220x over previous
#include <cuda_runtime.h>
#include <cstdint>

#define SORB  64
#define HID   256
#define BATCH 8192
#define LEN   1056
#define NSTEP 32
#define BPB   32        // batch elements per block (main kernel)

// Per-step precomputed quantities:
//   g_u[m][j]  = ( Σ_h W[h,start+j]·w0[h],  Σ_h W[h,start+j]·w1[h] )
//   g_cst[m]   = { c0=Σ hb·w0, c1=Σ hb·w1, Q0=Σ w0², Q1=Σ w1², Q01=Σ w0·w1 } (padded to 8)
__device__ float2 g_u[NSTEP][64];
__device__ float  g_cst[NSTEP][8];

__global__ __launch_bounds__(256)
void precompute_kernel(const float* __restrict__ W, const float* __restrict__ hb)
{
    const int m = blockIdx.x;
    const int k = 2 * m, start = m * (m + 1);
    __shared__ float sw0[HID], sw1[HID];
    const int tid = threadIdx.x;
    const int lane = tid & 31, wid = tid >> 5;

    // Stage w0, w1 (strided gather, once)
    {
        const float* p = W + (size_t)tid * LEN + start + k;
        sw0[tid] = p[0];
        sw1[tid] = p[1];
    }
    __syncthreads();

    if (tid < 64) {
        // u[m][tid]: coalesced over j=tid, loop h
        float a0 = 0.f, a1 = 0.f;
        if (tid < k) {
            const float* pw = W + start + tid;
            #pragma unroll 8
            for (int h = 0; h < HID; ++h) {
                const float wv = pw[(size_t)h * LEN];
                a0 = fmaf(wv, sw0[h], a0);
                a1 = fmaf(wv, sw1[h], a1);
            }
        }
        g_u[m][tid] = make_float2(a0, a1);
    } else if (wid >= 2 && wid <= 6) {
        // warps 2..6: the 5 constants, lane-parallel over h
        const int which = wid - 2;
        float acc = 0.f;
        #pragma unroll
        for (int hh = lane; hh < HID; hh += 32) {
            float a, b;
            if      (which == 0) { a = hb[hh];  b = sw0[hh]; }
            else if (which == 1) { a = hb[hh];  b = sw1[hh]; }
            else if (which == 2) { a = sw0[hh]; b = sw0[hh]; }
            else if (which == 3) { a = sw1[hh]; b = sw1[hh]; }
            else                 { a = sw0[hh]; b = sw1[hh]; }
            acc = fmaf(a, b, acc);
        }
        acc += __shfl_xor_sync(0xffffffffu, acc, 16);
        acc += __shfl_xor_sync(0xffffffffu, acc, 8);
        acc += __shfl_xor_sync(0xffffffffu, acc, 4);
        acc += __shfl_xor_sync(0xffffffffu, acc, 2);
        acc += __shfl_xor_sync(0xffffffffu, acc, 1);
        if (lane == 0) g_cst[m][which] = acc;
    }
}

// exp(L) for |L| <= 0.05, rel err < 5e-8
__device__ __forceinline__ float expq(float L) {
    return fmaf(L, fmaf(L, fmaf(L, 0.16666667f, 0.5f), 1.0f), 1.0f);
}

__global__ __launch_bounds__(256)
void rbm_main_kernel(const int* __restrict__ x, float* __restrict__ out)
{
    __shared__ float2   su[NSTEP][64];
    __shared__ float    sc[NSTEP][8];
    __shared__ unsigned sxlo[BPB], sxhi[BPB];
    __shared__ float    D0s[BPB][33], D1s[BPB][33];   // padded

    const int tid  = threadIdx.x;
    const int lane = tid & 31, wid = tid >> 5;
    const int b0   = blockIdx.x * BPB;

    // Stage per-step tables
    for (int idx = tid; idx < NSTEP * 64; idx += 256)
        ((float2*)su)[idx] = ((const float2*)g_u)[idx];
    if (tid < NSTEP * 8)
        ((float*)sc)[tid] = ((const float*)g_cst)[tid];

    // Pack x01 bits, coalesced: warp w handles rows 4w..4w+3
    #pragma unroll
    for (int r = 0; r < 4; ++r) {
        const int row = wid * 4 + r;
        const int v0 = x[(size_t)(b0 + row) * SORB + lane];
        const int v1 = x[(size_t)(b0 + row) * SORB + 32 + lane];
        const unsigned blo = __ballot_sync(0xffffffffu, v0 > 0);
        const unsigned bhi = __ballot_sync(0xffffffffu, v1 > 0);
        if (lane == 0) { sxlo[row] = blo; sxhi[row] = bhi; }
    }
    __syncthreads();

    // Phase A: thread = (b, g); g = tid>>5 owns steps m = g, g+8, g+16, g+24
    {
        const int b = tid & (BPB - 1);
        const int g = tid >> 5;                  // uniform per warp
        const unsigned lo = sxlo[b], hi = sxhi[b];
        #pragma unroll
        for (int mi = 0; mi < 4; ++mi) {
            const int m = g + 8 * mi;
            const int k = 2 * m;
            float d0 = sc[m][0], d1 = sc[m][1];
            const float2* pu = su[m];
            const int j1 = k < 32 ? k : 32;
            #pragma unroll 4
            for (int j = 0; j < j1; ++j) {
                const float msk = (float)((lo >> j) & 1u);
                const float2 uv = pu[j];
                d0 = fmaf(msk, uv.x, d0);
                d1 = fmaf(msk, uv.y, d1);
            }
            #pragma unroll 4
            for (int j = 32; j < k; ++j) {
                const float msk = (float)((hi >> (j - 32)) & 1u);
                const float2 uv = pu[j];
                d0 = fmaf(msk, uv.x, d0);
                d1 = fmaf(msk, uv.y, d1);
            }
            D0s[b][m] = d0; D1s[b][m] = d1;
        }
    }
    __syncthreads();

    // Phase B: cheap sequential chain, one thread per batch element
    if (tid < BPB) {
        const int b = tid;
        const unsigned lo = sxlo[b], hi = sxhi[b];
        float prob = 1.f;
        int nu = 0, nd = 0;
        #pragma unroll
        for (int m = 0; m < NSTEP; ++m) {
            const int k = 2 * m;
            const float d0 = D0s[b][m], d1 = D1s[b][m];
            const float L1 = -d0 - 0.5f * sc[m][2];
            const float L2 = -d1 - 0.5f * sc[m][3];
            const float L3 = L1 + L2 - sc[m][4];
            float v0 = 1.f, v1 = expq(L1), v2 = expq(L2), v3 = expq(L3);
            if (m >= 8) {                       // SYMMETRY && alpha_e <= k
                const int lower = m - 16;       // base + k/2
                const bool ou = nu < 16, uu = nu > lower;
                const bool od = nd < 16, ud = nd > lower;
                v0 = (uu && ud) ? v0 : 0.f;
                v1 = (ou && ud) ? v1 : 0.f;
                v2 = (uu && od) ? v2 : 0.f;
                v3 = (ou && od) ? v3 : 0.f;
            }
            const float n2 = v0*v0 + v1*v1 + v2*v2 + v3*v3;
            float inv = rsqrtf(fmaxf(n2, 1e-24f));
            inv = inv * fmaf(-0.5f * n2 * inv, inv, 1.5f);   // 1 Newton step
            int bu, bd;
            if (k < 32) { bu = (lo >> k) & 1;        bd = (lo >> (k + 1)) & 1; }
            else        { bu = (hi >> (k - 32)) & 1; bd = (hi >> (k - 31)) & 1; }
            const int st = bu + 2 * bd;
            const float vs = st == 0 ? v0 : st == 1 ? v1 : st == 2 ? v2 : v3;
            prob *= vs * inv;
            nu += bu; nd += bd;
        }
        out[b0 + b] = prob;
    }
}

extern "C" void kernel_launch(void* const* d_in, const int* in_sizes, int n_in,
                              void* d_out, int out_size)
{
    const int*   x   = (const int*)d_in[0];
    const float* W   = (const float*)d_in[1];
    const float* hb  = (const float*)d_in[2];
    float*       out = (float*)d_out;

    precompute_kernel<<<NSTEP, 256>>>(W, hb);
    rbm_main_kernel<<<BATCH / BPB, 256>>>(x, out);
}

// round 6
// speedup vs baseline: 25.0037x; 1.3153x over previous
#include <cuda_runtime.h>
#include <cstdint>

#define SORB  64
#define HID   256
#define BATCH 8192
#define LEN   1056
#define NSTEP 32

// Transposed per-step tables:
//   g_ut[j][m]  = ( Σ_h W[h,start(m)+j]·w0^m[h],  Σ_h W[h,start(m)+j]·w1^m[h] )   (0 if j >= 2m)
//   g_cstT[c][m], c = { 0:Σ hb·w0, 1:Σ hb·w1, 2:Σ w0², 3:Σ w1², 4:Σ w0·w1 }
__device__ float2 g_ut[64][32];
__device__ float  g_cstT[8][32];

__global__ __launch_bounds__(256)
void precompute_kernel(const float* __restrict__ W, const float* __restrict__ hb)
{
    const int m = blockIdx.x;
    const int k = 2 * m, start = m * (m + 1);
    __shared__ float sw0[HID], sw1[HID];
    __shared__ float p0[4][64], p1[4][64];
    const int tid = threadIdx.x;
    const int lane = tid & 31, wid = tid >> 5;

    // Stage w0, w1 (strided gather, once)
    {
        const float* p = W + (size_t)tid * LEN + start + k;
        sw0[tid] = p[0];
        sw1[tid] = p[1];
    }
    __syncthreads();

    // u[j]: 4 h-groups of 64 in parallel (cuts FMA chain 4x), coalesced over j
    {
        const int j = tid & 63, grp = tid >> 6;
        float a0 = 0.f, a1 = 0.f;
        if (j < k) {
            const float* pw = W + start + j + (size_t)grp * 64 * LEN;
            const float* s0 = sw0 + grp * 64;
            const float* s1 = sw1 + grp * 64;
            #pragma unroll
            for (int h = 0; h < 64; ++h) {
                const float wv = pw[(size_t)h * LEN];
                a0 = fmaf(wv, s0[h], a0);
                a1 = fmaf(wv, s1[h], a1);
            }
        }
        p0[grp][j] = a0;
        p1[grp][j] = a1;
    }
    __syncthreads();

    if (tid < 64) {
        g_ut[tid][m] = make_float2(p0[0][tid] + p0[1][tid] + p0[2][tid] + p0[3][tid],
                                   p1[0][tid] + p1[1][tid] + p1[2][tid] + p1[3][tid]);
    } else if (wid >= 2 && wid <= 6) {
        // warps 2..6: the 5 constants, lane-parallel over h
        const int which = wid - 2;
        float acc = 0.f;
        #pragma unroll
        for (int hh = lane; hh < HID; hh += 32) {
            float a, b;
            if      (which == 0) { a = hb[hh];  b = sw0[hh]; }
            else if (which == 1) { a = hb[hh];  b = sw1[hh]; }
            else if (which == 2) { a = sw0[hh]; b = sw0[hh]; }
            else if (which == 3) { a = sw1[hh]; b = sw1[hh]; }
            else                 { a = sw0[hh]; b = sw1[hh]; }
            acc = fmaf(a, b, acc);
        }
        acc += __shfl_xor_sync(0xffffffffu, acc, 16);
        acc += __shfl_xor_sync(0xffffffffu, acc, 8);
        acc += __shfl_xor_sync(0xffffffffu, acc, 4);
        acc += __shfl_xor_sync(0xffffffffu, acc, 2);
        acc += __shfl_xor_sync(0xffffffffu, acc, 1);
        if (lane == 0) g_cstT[which][m] = acc;
    }
}

// exp(L) for |L| <= 0.05, rel err < 5e-8
__device__ __forceinline__ float expq(float L) {
    return fmaf(L, fmaf(L, fmaf(L, 0.16666667f, 0.5f), 1.0f), 1.0f);
}

// One warp per batch element; lane = step m. No serial chain, no phase barriers.
__global__ __launch_bounds__(512)
void rbm_main_kernel(const int* __restrict__ x, float* __restrict__ out)
{
    __shared__ float2 sut[64][32];
    __shared__ float  sct[8][32];

    const int tid  = threadIdx.x;
    const int lane = tid & 31, wid = tid >> 5;

    // Stage tables (shared by 16 warps)
    for (int idx = tid; idx < 64 * 32; idx += 512)
        ((float2*)sut)[idx] = ((const float2*)g_ut)[idx];
    if (tid < 8 * 32)
        ((float*)sct)[tid] = ((const float*)g_cstT)[tid];

    // This warp's batch element: pack x bits (warp-uniform words via ballot)
    const int b  = blockIdx.x * 16 + wid;
    const int v0 = x[(size_t)b * SORB + lane];
    const int v1 = x[(size_t)b * SORB + 32 + lane];
    const unsigned lo = __ballot_sync(0xffffffffu, v0 > 0);
    const unsigned hi = __ballot_sync(0xffffffffu, v1 > 0);

    __syncthreads();

    const int m = lane;
    const int k = 2 * m;

    // d0/d1: walk set bits of the uniform x words; lanes predicate on j < k
    float d0 = sct[0][m], d1 = sct[1][m];
    unsigned w = lo;
    while (w) {
        const int j = __ffs(w) - 1;    // warp-uniform
        w &= w - 1;
        const float2 uv = sut[j][m];   // conflict-free: lanes consecutive
        if (j < k) { d0 += uv.x; d1 += uv.y; }
    }
    w = hi;
    while (w) {
        const int j = __ffs(w) - 1;
        w &= w - 1;
        const float2 uv = sut[j + 32][m];
        if (j + 32 < k) { d0 += uv.x; d1 += uv.y; }
    }

    // Per-step term
    const float L1 = -d0 - 0.5f * sct[2][m];
    const float L2 = -d1 - 0.5f * sct[3][m];
    const float L3 = L1 + L2 - sct[4][m];
    float v0f = 1.f, v1f = expq(L1), v2f = expq(L2), v3f = expq(L3);

    // nu/nd directly from popcounts of even/odd bits below position k
    const unsigned mlo = (k >= 32) ? 0xffffffffu : ((1u << k) - 1u);
    const unsigned mhi = (k > 32) ? ((1u << (k - 32)) - 1u) : 0u;
    const int nu = __popc(lo & 0x55555555u & mlo) + __popc(hi & 0x55555555u & mhi);
    const int nd = __popc(lo & 0xAAAAAAAAu & mlo) + __popc(hi & 0xAAAAAAAAu & mhi);

    if (m >= 8) {                        // SYMMETRY && alpha_e <= k
        const int lower = m - 16;        // base + k/2
        const bool ou = nu < 16, uu = nu > lower;
        const bool od = nd < 16, ud = nd > lower;
        v0f = (uu && ud) ? v0f : 0.f;
        v1f = (ou && ud) ? v1f : 0.f;
        v2f = (uu && od) ? v2f : 0.f;
        v3f = (ou && od) ? v3f : 0.f;
    }

    const float n2 = v0f*v0f + v1f*v1f + v2f*v2f + v3f*v3f;
    float inv = rsqrtf(fmaxf(n2, 1e-24f));
    inv = inv * fmaf(-0.5f * n2 * inv, inv, 1.5f);   // 1 Newton step

    const int bu = (k < 32) ? ((lo >> k) & 1)        : ((hi >> (k - 32)) & 1);
    const int bd = (k < 32) ? ((lo >> (k + 1)) & 1)  : ((hi >> (k - 31)) & 1);
    const int st = bu + 2 * bd;
    const float vs = st == 0 ? v0f : st == 1 ? v1f : st == 2 ? v2f : v3f;

    float term = vs * inv;

    // Butterfly product over the 32 steps
    term *= __shfl_xor_sync(0xffffffffu, term, 16);
    term *= __shfl_xor_sync(0xffffffffu, term, 8);
    term *= __shfl_xor_sync(0xffffffffu, term, 4);
    term *= __shfl_xor_sync(0xffffffffu, term, 2);
    term *= __shfl_xor_sync(0xffffffffu, term, 1);

    if (lane == 0) out[b] = term;
}

extern "C" void kernel_launch(void* const* d_in, const int* in_sizes, int n_in,
                              void* d_out, int out_size)
{
    const int*   x   = (const int*)d_in[0];
    const float* W   = (const float*)d_in[1];
    const float* hb  = (const float*)d_in[2];
    float*       out = (float*)d_out;

    precompute_kernel<<<NSTEP, 256>>>(W, hb);
    rbm_main_kernel<<<BATCH / 16, 512>>>(x, out);
}

// round 7
// speedup vs baseline: 29.0087x; 1.1602x over previous
#include <cuda_runtime.h>
#include <cstdint>

#define SORB  64
#define HID   256
#define BATCH 8192
#define LEN   1056
#define NSTEP 32
#define TB    4      // batch elements per warp

// Transposed, NEGATED per-step tables (zero for j >= 2m):
//   g_ut[j][m] = ( -Σ_h W[h,start+j]·w0, -Σ_h W[h,start+j]·w1 )
//   g_cstT[0][m] = -Σhb·w0 - 0.5Σw0²   (L1 base)
//   g_cstT[1][m] = -Σhb·w1 - 0.5Σw1²   (L2 base)
//   g_cstT[2][m] = -Σw0·w1             (L3 = L1+L2+this)
__device__ float2 g_ut[64][32];
__device__ float  g_cstT[4][32];

__global__ __launch_bounds__(512)
void precompute_kernel(const float* __restrict__ W, const float* __restrict__ hb)
{
    const int m = blockIdx.x;
    const int k = 2 * m, start = m * (m + 1);
    __shared__ float sw0[HID], sw1[HID];
    __shared__ float p0[8][64], p1[8][64];
    __shared__ float cst[5];
    const int tid = threadIdx.x;
    const int lane = tid & 31, wid = tid >> 5;

    if (tid < HID) {                       // stage w0,w1 (strided gather, once)
        const float* p = W + (size_t)tid * LEN + start + k;
        sw0[tid] = p[0];
        sw1[tid] = p[1];
    }
    __syncthreads();

    // u-partials: 8 h-groups of 32, coalesced over j
    {
        const int j = tid & 63, grp = tid >> 6;
        float a0 = 0.f, a1 = 0.f;
        if (j < k) {
            const float* pw = W + start + j + (size_t)grp * 32 * LEN;
            const float* s0 = sw0 + grp * 32;
            const float* s1 = sw1 + grp * 32;
            #pragma unroll
            for (int h = 0; h < 32; ++h) {
                const float wv = pw[(size_t)h * LEN];
                a0 = fmaf(wv, s0[h], a0);
                a1 = fmaf(wv, s1[h], a1);
            }
        }
        p0[grp][j] = a0;
        p1[grp][j] = a1;
    }
    // constants in warps 8..12 (independent of p-arrays)
    if (wid >= 8 && wid <= 12) {
        const int which = wid - 8;
        float acc = 0.f;
        #pragma unroll
        for (int hh = lane; hh < HID; hh += 32) {
            float a, b;
            if      (which == 0) { a = hb[hh];  b = sw0[hh]; }
            else if (which == 1) { a = hb[hh];  b = sw1[hh]; }
            else if (which == 2) { a = sw0[hh]; b = sw0[hh]; }
            else if (which == 3) { a = sw1[hh]; b = sw1[hh]; }
            else                 { a = sw0[hh]; b = sw1[hh]; }
            acc = fmaf(a, b, acc);
        }
        acc += __shfl_xor_sync(0xffffffffu, acc, 16);
        acc += __shfl_xor_sync(0xffffffffu, acc, 8);
        acc += __shfl_xor_sync(0xffffffffu, acc, 4);
        acc += __shfl_xor_sync(0xffffffffu, acc, 2);
        acc += __shfl_xor_sync(0xffffffffu, acc, 1);
        if (lane == 0) cst[which] = acc;
    }
    __syncthreads();

    if (tid < 64) {
        float s0 = 0.f, s1 = 0.f;
        #pragma unroll
        for (int g = 0; g < 8; ++g) { s0 += p0[g][tid]; s1 += p1[g][tid]; }
        g_ut[tid][m] = make_float2(-s0, -s1);
    } else if (tid == 64) {
        g_cstT[0][m] = -cst[0] - 0.5f * cst[2];
        g_cstT[1][m] = -cst[1] - 0.5f * cst[3];
        g_cstT[2][m] = -cst[4];
    }
}

// exp(L) for |L| <= 0.05, rel err < 5e-8
__device__ __forceinline__ float expq(float L) {
    return fmaf(L, fmaf(L, fmaf(L, 0.16666667f, 0.5f), 1.0f), 1.0f);
}

// One warp per TB batch elements; lane = step m. Dense unrolled, branch-free.
__global__ __launch_bounds__(256)
void rbm_main_kernel(const int* __restrict__ x, float* __restrict__ out)
{
    __shared__ float2 sut[64][32];
    __shared__ float  sct[4][32];

    const int tid  = threadIdx.x;
    const int lane = tid & 31, wid = tid >> 5;

    // Stage tables (2048 float2 / 256 thr = 8 each)
    #pragma unroll
    for (int r = 0; r < 8; ++r)
        ((float2*)sut)[r * 256 + tid] = ((const float2*)g_ut)[r * 256 + tid];
    if (tid < 4 * 32)
        ((float*)sct)[tid] = ((const float*)g_cstT)[tid];

    // This warp's TB batch elements: pack bits (warp-uniform words)
    const int b0 = (blockIdx.x * 8 + wid) * TB;
    unsigned lo[TB], hi[TB];
    #pragma unroll
    for (int t = 0; t < TB; ++t) {
        const int v0 = x[(size_t)(b0 + t) * SORB + lane];
        const int v1 = x[(size_t)(b0 + t) * SORB + 32 + lane];
        lo[t] = __ballot_sync(0xffffffffu, v0 > 0);
        hi[t] = __ballot_sync(0xffffffffu, v1 > 0);
    }
    __syncthreads();

    const int m = lane;
    const int k = 2 * m;

    // Dense accumulation: 64 shared loads serve TB elements, no branches.
    float L1[TB], L2[TB];
    #pragma unroll
    for (int t = 0; t < TB; ++t) { L1[t] = sct[0][m]; L2[t] = sct[1][m]; }

    #pragma unroll
    for (int j = 0; j < 32; ++j) {
        const float2 uv = sut[j][m];
        #pragma unroll
        for (int t = 0; t < TB; ++t) {
            const float msk = __uint_as_float(((lo[t] >> j) & 1u) * 0x3f800000u);
            L1[t] = fmaf(msk, uv.x, L1[t]);
            L2[t] = fmaf(msk, uv.y, L2[t]);
        }
    }
    #pragma unroll
    for (int j = 0; j < 32; ++j) {
        const float2 uv = sut[j + 32][m];
        #pragma unroll
        for (int t = 0; t < TB; ++t) {
            const float msk = __uint_as_float(((hi[t] >> j) & 1u) * 0x3f800000u);
            L1[t] = fmaf(msk, uv.x, L1[t]);
            L2[t] = fmaf(msk, uv.y, L2[t]);
        }
    }

    // masks for popcounts below position k (lane-dependent, batch-independent)
    const unsigned mlo = (k >= 32) ? 0xffffffffu : ((1u << k) - 1u);
    const unsigned mhi = (k > 32) ? ((1u << (k - 32)) - 1u) : 0u;
    const float negQ01 = sct[2][m];

    float terms[TB];
    #pragma unroll
    for (int t = 0; t < TB; ++t) {
        const float L3 = L1[t] + L2[t] + negQ01;
        float v0f = 1.f, v1f = expq(L1[t]), v2f = expq(L2[t]), v3f = expq(L3);

        const int nu = __popc(lo[t] & 0x55555555u & mlo) + __popc(hi[t] & 0x55555555u & mhi);
        const int nd = __popc(lo[t] & 0xAAAAAAAAu & mlo) + __popc(hi[t] & 0xAAAAAAAAu & mhi);

        if (m >= 8) {                        // SYMMETRY && alpha_e <= k
            const int lower = m - 16;        // base + k/2
            const bool ou = nu < 16, uu = nu > lower;
            const bool od = nd < 16, ud = nd > lower;
            v0f = (uu && ud) ? v0f : 0.f;
            v1f = (ou && ud) ? v1f : 0.f;
            v2f = (uu && od) ? v2f : 0.f;
            v3f = (ou && od) ? v3f : 0.f;
        }

        const float n2 = v0f*v0f + v1f*v1f + v2f*v2f + v3f*v3f;
        float inv = rsqrtf(fmaxf(n2, 1e-24f));
        inv = inv * fmaf(-0.5f * n2 * inv, inv, 1.5f);   // Newton

        const int bu = (k < 32) ? ((lo[t] >> k) & 1)       : ((hi[t] >> (k - 32)) & 1);
        const int bd = (k < 32) ? ((lo[t] >> (k + 1)) & 1) : ((hi[t] >> (k - 31)) & 1);
        const int st = bu + 2 * bd;
        const float vs = st == 0 ? v0f : st == 1 ? v1f : st == 2 ? v2f : v3f;

        float term = vs * inv;
        term *= __shfl_xor_sync(0xffffffffu, term, 16);
        term *= __shfl_xor_sync(0xffffffffu, term, 8);
        term *= __shfl_xor_sync(0xffffffffu, term, 4);
        term *= __shfl_xor_sync(0xffffffffu, term, 2);
        term *= __shfl_xor_sync(0xffffffffu, term, 1);
        terms[t] = term;
    }

    // coalesced-ish output: lanes 0..TB-1 write the TB results
    float o = terms[0];
    #pragma unroll
    for (int t = 1; t < TB; ++t) o = (lane == t) ? terms[t] : o;
    if (lane < TB) out[b0 + lane] = o;
}

extern "C" void kernel_launch(void* const* d_in, const int* in_sizes, int n_in,
                              void* d_out, int out_size)
{
    const int*   x   = (const int*)d_in[0];
    const float* W   = (const float*)d_in[1];
    const float* hb  = (const float*)d_in[2];
    float*       out = (float*)d_out;

    precompute_kernel<<<NSTEP, 512>>>(W, hb);
    rbm_main_kernel<<<BATCH / (8 * TB), 256>>>(x, out);
}